// round 16
// baseline (speedup 1.0000x reference)
#include <cuda_runtime.h>

#define BETA   0.9f
#define NT     32                 // time steps
#define T8     8                  // steps per reduce chunk
#define TILE_Q 256                // pooled (q) positions per CTA
#define NTILE  8
#define NTHR   512
#define SROW   4104               // spike row: [2 guard][4096 pos][6 pad]

// dynamic smem layout for K2 (bytes)
#define LUT_BYTES (3 * 256 * 4 * 8 * 4)        // 98304: lutR[3][256][4 copies][8 co]
#define RAW_OFF   LUT_BYTES
#define RAW_BYTES (2 * T8 * 128 * 8)           // 16384: raw[2][T8][128] float2
#define SMEM_TOTAL (RAW_OFF + RAW_BYTES)       // 114688 -> 2 CTAs/SM

// layer-1 spike bytes: [b][t][SROW], position p at byte p+2
__device__ unsigned char g_spk[256 * NT * SROW];
// [b][tile][t][o] partial FC sums
__device__ float g_partial[256 * NTILE * NT * 2];

__device__ __forceinline__ float4 add4(float4 a, float4 b) {
    return make_float4(a.x + b.x, a.y + b.y, a.z + b.z, a.w + b.w);
}
__device__ __forceinline__ float4 max4(float4 a, float4 b) {
    return make_float4(fmaxf(a.x, b.x), fmaxf(a.y, b.y),
                       fmaxf(a.z, b.z), fmaxf(a.w, b.w));
}

// ==== K1: layer-1 conv1+pool+LIF, 2 positions/thread, u16 stores ====
__global__ __launch_bounds__(512) void snn_l1(
    const float* __restrict__ x,     // [256,1,8192]
    const float* __restrict__ w1,    // [8,1,3]
    const float* __restrict__ b1,    // [8]
    const float* __restrict__ th1p)
{
    const int blk  = blockIdx.x;
    const int b    = blk >> 2;
    const int pos0 = ((blk & 3) * 512 + threadIdx.x) * 2;   // even, 0..4094
    const float th1 = *th1p;

    const float* xb = x + b * 8192;
    const int xi = 2 * pos0;
    const float x0 = (pos0 > 0) ? xb[xi - 1] : 0.f;
    const float x1 = xb[xi];
    const float x2 = xb[xi + 1];
    const float x3 = xb[xi + 2];
    const float x4 = xb[xi + 3];
    const float x5 = (xi + 4 < 8192) ? xb[xi + 4] : 0.f;

    float cur[2][8], m[2][8];
    #pragma unroll
    for (int c = 0; c < 8; c++) {
        const float wa = w1[3 * c], wb = w1[3 * c + 1], wc = w1[3 * c + 2];
        const float y00 = wa * x0 + wb * x1 + wc * x2;
        const float y01 = wa * x1 + wb * x2 + wc * x3;
        const float y10 = wa * x2 + wb * x3 + wc * x4;
        const float y11 = wa * x3 + wb * x4 + wc * x5;
        cur[0][c] = fmaxf(y00, y01) + b1[c];
        cur[1][c] = fmaxf(y10, y11) + b1[c];
        m[0][c] = 0.f; m[1][c] = 0.f;
    }
    unsigned sp = 0;   // bits [0:8) = pos0, bits [8:16) = pos0+1 (prev spikes)

    unsigned char* rowp = g_spk + (b * NT) * SROW + pos0 + 2;
    #pragma unroll 4
    for (int t = 0; t < NT; t++) {
        unsigned nsp = 0;
        #pragma unroll
        for (int pp = 0; pp < 2; pp++) {
            #pragma unroll
            for (int c = 0; c < 8; c++) {
                const int bit = 8 * pp + c;
                float mm = fmaf(BETA, m[pp][c], cur[pp][c]);
                if ((sp >> bit) & 1) mm -= th1;
                m[pp][c] = mm;
                if (mm > th1) nsp |= (1u << bit);
            }
        }
        sp = nsp;
        *reinterpret_cast<unsigned short*>(rowp + t * SROW) =
            (unsigned short)nsp;
    }

    // guard bytes per (b, t): front bytes 0..1, tail bytes 4098..4103
    if ((blk & 3) == 0 && threadIdx.x < NT) {
        unsigned char* g0 = g_spk + (b * NT + threadIdx.x) * SROW;
        *reinterpret_cast<unsigned short*>(g0) = 0;
        *reinterpret_cast<unsigned short*>(g0 + 4098) = 0;
        *reinterpret_cast<unsigned*>(g0 + 4100) = 0;
    }
}

// ==== K2: conv2(LUT)+pool+LIF2+FC, consume-only, 4 barriers total ====
__global__ __launch_bounds__(NTHR, 2) void snn_main(
    const float* __restrict__ w2,    // [8,8,3]
    const float* __restrict__ b2,    // [8]
    const float* __restrict__ fcw,   // [2,16384]
    const float* __restrict__ th2p)
{
    extern __shared__ __align__(16) unsigned char smem[];
    float*  lutR = reinterpret_cast<float*>(smem);            // [3][256][4][8]
    float2* raw  = reinterpret_cast<float2*>(smem + RAW_OFF); // [2][T8][128]

    const int blk  = blockIdx.x;
    const int b    = blk >> 3;
    const int tile = blk & 7;
    const int tid  = threadIdx.x;
    const int q0   = tile * TILE_Q;
    const float th2 = *th2p;

    // ---- Build conv2 byte-LUTs, replicated 4x (provably conflict-free):
    // lutR[k][s][j][co] = sum_{ci in s} w2[co][ci][k]  (+ bias folded into k=1)
    for (int idx = tid; idx < 3 * 256; idx += NTHR) {
        const int k = idx >> 8;
        const int s = idx & 255;
        float acc[8];
        #pragma unroll
        for (int co = 0; co < 8; co++) acc[co] = (k == 1) ? b2[co] : 0.f;
        #pragma unroll
        for (int ci = 0; ci < 8; ci++) {
            if ((s >> ci) & 1) {
                #pragma unroll
                for (int co = 0; co < 8; co++)
                    acc[co] += w2[(co * 8 + ci) * 3 + k];
            }
        }
        float4* row = reinterpret_cast<float4*>(lutR + idx * 32);
        const float4 lo = make_float4(acc[0], acc[1], acc[2], acc[3]);
        const float4 hi = make_float4(acc[4], acc[5], acc[6], acc[7]);
        #pragma unroll
        for (int j = 0; j < 4; j++) { row[2 * j] = lo; row[2 * j + 1] = hi; }
    }

    // ---- role: q = tid>>1, h = tid&1 (own co 4h..4h+3), LUT copy j = q&3
    // -> every 8-lane LDS.128 phase hits 8 distinct 16B slots (conflict-free).
    const int qloc = tid >> 1;
    const int h    = tid & 1;
    const int qg   = q0 + qloc;
    const float* lutT = lutR + (qloc & 3) * 8 + 4 * h;

    float fw0[4], fw1[4], m2[4];
    bool sp2[4];
    #pragma unroll
    for (int j = 0; j < 4; j++) {
        fw0[j] = fcw[(4 * h + j) * 2048 + qg];
        fw1[j] = fcw[16384 + (4 * h + j) * 2048 + qg];
        m2[j] = 0.f;
        sp2[j] = false;
    }

    const int lane = tid & 31, wrp = tid >> 5;
    const int off   = 2 * qg + 1;             // byte idx of pos 2qg-1 (FRONT=2)
    const int wbase = off & ~3;
    const int fsh   = (off & 3) * 8;          // 8 or 24
    const unsigned char* spk_b = g_spk + (b * NT) * SROW;
    float* gpart = g_partial + ((b * NTILE + tile) * NT) * 2;
    __syncthreads();

    // -- prime the spike-word pipeline (t = 0)
    unsigned cw0 = *reinterpret_cast<const unsigned*>(spk_b + wbase);
    unsigned cw1 = *reinterpret_cast<const unsigned*>(spk_b + wbase + 4);

    // ==== flat t loop; ONE barrier per 8-step chunk; reduce overlapped
    #pragma unroll 8
    for (int t = 0; t < NT; t++) {
        const unsigned sword = __funnelshift_r(cw0, cw1, fsh);
        if (t + 1 < NT) {   // prefetch next step's words (hides L2 latency)
            const unsigned char* nrow = spk_b + (t + 1) * SROW;
            cw0 = *reinterpret_cast<const unsigned*>(nrow + wbase);
            cw1 = *reinterpret_cast<const unsigned*>(nrow + wbase + 4);
        }
        const int x0o = (int)(sword & 255u) << 5;
        const int x1o = (int)((sword >> 8) & 255u) << 5;
        const int x2o = (int)((sword >> 16) & 255u) << 5;
        const int x3o = (int)(sword >> 24) << 5;

        const float4 A0 = *reinterpret_cast<const float4*>(lutT + x0o);
        const float4 A1 = *reinterpret_cast<const float4*>(lutT + 8192 + x1o);
        const float4 A2 = *reinterpret_cast<const float4*>(lutT + 16384 + x2o);
        const float4 B0 = *reinterpret_cast<const float4*>(lutT + x1o);
        const float4 B1 = *reinterpret_cast<const float4*>(lutT + 8192 + x2o);
        const float4 B2 = *reinterpret_cast<const float4*>(lutT + 16384 + x3o);

        const float4 cv = max4(add4(add4(A0, A1), A2),
                               add4(add4(B0, B1), B2));
        const float cur2[4] = {cv.x, cv.y, cv.z, cv.w};

        float pacc0 = 0.f, pacc1 = 0.f;
        #pragma unroll
        for (int j = 0; j < 4; j++) {
            float mm = fmaf(BETA, m2[j], cur2[j]);
            if (sp2[j]) mm -= th2;            // reset = previous spike
            m2[j] = mm;
            sp2[j] = mm > th2;
            if (sp2[j]) { pacc0 += fw0[j]; pacc1 += fw1[j]; }
        }
        // compress {l, l^8, l^16, l^24} -> lanes 0..7 store one STS.64
        pacc0 += __shfl_xor_sync(0xffffffffu, pacc0, 16);
        pacc1 += __shfl_xor_sync(0xffffffffu, pacc1, 16);
        pacc0 += __shfl_xor_sync(0xffffffffu, pacc0, 8);
        pacc1 += __shfl_xor_sync(0xffffffffu, pacc1, 8);
        if (lane < 8)
            raw[((t >> 3) & 1) * (T8 * 128) + (t & 7) * 128 + wrp * 8 + lane] =
                make_float2(pacc0, pacc1);

        if ((t & 7) == 7) {
            __syncthreads();
            // reduce this chunk (warps 0..15) writing g_partial directly;
            // other warps proceed to the next chunk's other raw buffer.
            if (wrp < 2 * T8) {
                const int tt = wrp >> 1, o = wrp & 1;
                const float* rf = reinterpret_cast<const float*>(
                    raw + ((t >> 3) & 1) * (T8 * 128) + tt * 128) + o;
                float s = 0.f;
                #pragma unroll
                for (int k = 0; k < 4; k++)
                    s += rf[(lane + 32 * k) * 2];
                #pragma unroll
                for (int offx = 16; offx > 0; offx >>= 1)
                    s += __shfl_xor_sync(0xffffffffu, s, offx);
                if (lane == 0)
                    gpart[((t & ~7) + tt) * 2 + o] = s;
            }
        }
    }
}

__global__ __launch_bounds__(64) void snn_final(
    const float* __restrict__ fcb,
    const float* __restrict__ thop,
    float* __restrict__ out)
{
    __shared__ float sm[NT][2];
    const int b = blockIdx.x;
    const int tid = threadIdx.x;

    {
        const int t = tid >> 1, o = tid & 1;
        float s = 0.f;
        #pragma unroll
        for (int tile = 0; tile < NTILE; tile++)
            s += g_partial[((b * NTILE + tile) * NT + t) * 2 + o];
        sm[t][o] = s;
    }
    __syncthreads();

    if (tid < 2) {
        const int o = tid;
        const float tho = *thop;
        const float fb = fcb[o];
        float mo = 0.f;
        for (int t = 0; t < NT; t++) {
            const float c = sm[t][o] + fb;
            const bool r = mo > tho;
            mo = BETA * mo + c;
            if (r) mo -= tho;
            const int base = (t * 256 + b) * 2 + o;
            out[base] = (mo > tho) ? 1.f : 0.f;   // spk_rec
            out[16384 + base] = mo;               // mem_rec
        }
    }
}

extern "C" void kernel_launch(void* const* d_in, const int* in_sizes, int n_in,
                              void* d_out, int out_size)
{
    const float* x    = (const float*)d_in[0];
    const float* w1   = (const float*)d_in[1];
    const float* b1   = (const float*)d_in[2];
    const float* w2   = (const float*)d_in[3];
    const float* b2   = (const float*)d_in[4];
    const float* fcw  = (const float*)d_in[5];
    const float* fcb  = (const float*)d_in[6];
    const float* th1  = (const float*)d_in[7];
    const float* th2  = (const float*)d_in[8];
    const float* tho  = (const float*)d_in[9];
    float* out = (float*)d_out;

    cudaFuncSetAttribute(snn_main, cudaFuncAttributeMaxDynamicSharedMemorySize,
                         SMEM_TOTAL);

    snn_l1<<<256 * 4, 512>>>(x, w1, b1, th1);
    snn_main<<<256 * NTILE, NTHR, SMEM_TOTAL>>>(w2, b2, fcw, th2);
    snn_final<<<256, 64>>>(fcb, tho, out);
}

// round 17
// speedup vs baseline: 1.0247x; 1.0247x over previous
#include <cuda_runtime.h>

#define BETA   0.9f
#define NT     32                 // time steps
#define T8     8                  // steps per reduce chunk
#define TILE_Q 256                // pooled (q) positions per CTA
#define NTILE  8
#define NTHR   512
#define SROW   4104               // spike row: [2 guard][4096 pos][6 pad]

// dynamic smem layout for K2 (bytes)
#define LUT_BYTES (3 * 256 * 4 * 8 * 4)        // 98304: lutR[3][256][4 copies][8 co]
#define RAW_OFF   LUT_BYTES
#define RAW_BYTES (2 * T8 * 128 * 8)           // 16384: raw[2][T8][128] float2
#define SMEM_TOTAL (RAW_OFF + RAW_BYTES)       // 114688 -> 2 CTAs/SM

// layer-1 spike bytes: [b][t][SROW], position p at byte p+2
__device__ unsigned char g_spk[256 * NT * SROW];
// [b][tile][t][o] partial FC sums
__device__ float g_partial[256 * NTILE * NT * 2];

__device__ __forceinline__ float4 add4(float4 a, float4 b) {
    return make_float4(a.x + b.x, a.y + b.y, a.z + b.z, a.w + b.w);
}
__device__ __forceinline__ float4 max4(float4 a, float4 b) {
    return make_float4(fmaxf(a.x, b.x), fmaxf(a.y, b.y),
                       fmaxf(a.z, b.z), fmaxf(a.w, b.w));
}

// ==== K1: layer-1 conv1+pool+LIF, 2 positions/thread, u16 stores ====
// (R15 measured version: bool spike state -> predicate registers, no bit ALU)
__global__ __launch_bounds__(512) void snn_l1(
    const float* __restrict__ x,     // [256,1,8192]
    const float* __restrict__ w1,    // [8,1,3]
    const float* __restrict__ b1,    // [8]
    const float* __restrict__ th1p)
{
    const int blk  = blockIdx.x;
    const int b    = blk >> 2;
    const int pos0 = ((blk & 3) * 512 + threadIdx.x) * 2;   // even, 0..4094
    const float th1 = *th1p;

    const float* xb = x + b * 8192;
    const int xi = 2 * pos0;
    const float x0 = (pos0 > 0) ? xb[xi - 1] : 0.f;
    const float x1 = xb[xi];
    const float x2 = xb[xi + 1];
    const float x3 = xb[xi + 2];
    const float x4 = xb[xi + 3];
    const float x5 = (xi + 4 < 8192) ? xb[xi + 4] : 0.f;

    float cur[2][8], m[2][8];
    bool  sp[2][8];
    #pragma unroll
    for (int c = 0; c < 8; c++) {
        const float wa = w1[3 * c], wb = w1[3 * c + 1], wc = w1[3 * c + 2];
        const float y00 = wa * x0 + wb * x1 + wc * x2;
        const float y01 = wa * x1 + wb * x2 + wc * x3;
        const float y10 = wa * x2 + wb * x3 + wc * x4;
        const float y11 = wa * x3 + wb * x4 + wc * x5;
        cur[0][c] = fmaxf(y00, y01) + b1[c];
        cur[1][c] = fmaxf(y10, y11) + b1[c];
        m[0][c] = 0.f; m[1][c] = 0.f;
        sp[0][c] = false; sp[1][c] = false;
    }

    unsigned char* rowp = g_spk + (b * NT) * SROW + pos0 + 2;
    #pragma unroll 4
    for (int t = 0; t < NT; t++) {
        unsigned us = 0;
        #pragma unroll
        for (int pp = 0; pp < 2; pp++) {
            unsigned byte = 0;
            #pragma unroll
            for (int c = 0; c < 8; c++) {
                float mm = fmaf(BETA, m[pp][c], cur[pp][c]);
                if (sp[pp][c]) mm -= th1;
                m[pp][c] = mm;
                sp[pp][c] = mm > th1;
                if (sp[pp][c]) byte |= (1u << c);
            }
            us |= byte << (8 * pp);
        }
        *reinterpret_cast<unsigned short*>(rowp + t * SROW) =
            (unsigned short)us;
    }

    // guard bytes per (b, t): front bytes 0..1, tail bytes 4098..4103
    if ((blk & 3) == 0 && threadIdx.x < NT) {
        unsigned char* g0 = g_spk + (b * NT + threadIdx.x) * SROW;
        *reinterpret_cast<unsigned short*>(g0) = 0;
        *reinterpret_cast<unsigned short*>(g0 + 4098) = 0;
        *reinterpret_cast<unsigned*>(g0 + 4100) = 0;
    }
}

// ==== K2: conv2(LUT)+pool+LIF2+FC, consume-only, 4 barriers total ====
__global__ __launch_bounds__(NTHR, 2) void snn_main(
    const float* __restrict__ w2,    // [8,8,3]
    const float* __restrict__ b2,    // [8]
    const float* __restrict__ fcw,   // [2,16384]
    const float* __restrict__ th2p)
{
    extern __shared__ __align__(16) unsigned char smem[];
    float*  lutR = reinterpret_cast<float*>(smem);            // [3][256][4][8]
    float2* raw  = reinterpret_cast<float2*>(smem + RAW_OFF); // [2][T8][128]

    const int blk  = blockIdx.x;
    const int b    = blk >> 3;
    const int tile = blk & 7;
    const int tid  = threadIdx.x;
    const int q0   = tile * TILE_Q;
    const float th2 = *th2p;

    // ---- Build conv2 byte-LUTs, replicated 4x (provably conflict-free):
    // lutR[k][s][j][co] = sum_{ci in s} w2[co][ci][k]  (+ bias folded into k=1)
    for (int idx = tid; idx < 3 * 256; idx += NTHR) {
        const int k = idx >> 8;
        const int s = idx & 255;
        float acc[8];
        #pragma unroll
        for (int co = 0; co < 8; co++) acc[co] = (k == 1) ? b2[co] : 0.f;
        #pragma unroll
        for (int ci = 0; ci < 8; ci++) {
            if ((s >> ci) & 1) {
                #pragma unroll
                for (int co = 0; co < 8; co++)
                    acc[co] += w2[(co * 8 + ci) * 3 + k];
            }
        }
        float4* row = reinterpret_cast<float4*>(lutR + idx * 32);
        const float4 lo = make_float4(acc[0], acc[1], acc[2], acc[3]);
        const float4 hi = make_float4(acc[4], acc[5], acc[6], acc[7]);
        #pragma unroll
        for (int j = 0; j < 4; j++) { row[2 * j] = lo; row[2 * j + 1] = hi; }
    }

    // ---- role: q = tid>>1, h = tid&1 (own co 4h..4h+3), LUT copy j = q&3
    // -> every 8-lane LDS.128 phase hits 8 distinct 16B slots (conflict-free).
    const int qloc = tid >> 1;
    const int h    = tid & 1;
    const int qg   = q0 + qloc;
    const float* lutT = lutR + (qloc & 3) * 8 + 4 * h;

    float fw0[4], fw1[4], m2[4];
    bool sp2[4];
    #pragma unroll
    for (int j = 0; j < 4; j++) {
        fw0[j] = fcw[(4 * h + j) * 2048 + qg];
        fw1[j] = fcw[16384 + (4 * h + j) * 2048 + qg];
        m2[j] = 0.f;
        sp2[j] = false;
    }

    const int lane = tid & 31, wrp = tid >> 5;
    const int off   = 2 * qg + 1;             // byte idx of pos 2qg-1 (FRONT=2)
    const int wbase = off & ~3;
    const int fsh   = (off & 3) * 8;          // 8 or 24
    const unsigned char* spk_b = g_spk + (b * NT) * SROW;
    float* gpart = g_partial + ((b * NTILE + tile) * NT) * 2;
    __syncthreads();

    // -- prime the spike-word pipeline (t = 0)
    unsigned cw0 = *reinterpret_cast<const unsigned*>(spk_b + wbase);
    unsigned cw1 = *reinterpret_cast<const unsigned*>(spk_b + wbase + 4);

    // ==== flat t loop; ONE barrier per 8-step chunk; reduce overlapped
    #pragma unroll 8
    for (int t = 0; t < NT; t++) {
        const unsigned sword = __funnelshift_r(cw0, cw1, fsh);
        if (t + 1 < NT) {   // prefetch next step's words (hides L2 latency)
            const unsigned char* nrow = spk_b + (t + 1) * SROW;
            cw0 = *reinterpret_cast<const unsigned*>(nrow + wbase);
            cw1 = *reinterpret_cast<const unsigned*>(nrow + wbase + 4);
        }
        const int x0o = (int)(sword & 255u) << 5;
        const int x1o = (int)((sword >> 8) & 255u) << 5;
        const int x2o = (int)((sword >> 16) & 255u) << 5;
        const int x3o = (int)(sword >> 24) << 5;

        const float4 A0 = *reinterpret_cast<const float4*>(lutT + x0o);
        const float4 A1 = *reinterpret_cast<const float4*>(lutT + 8192 + x1o);
        const float4 A2 = *reinterpret_cast<const float4*>(lutT + 16384 + x2o);
        const float4 B0 = *reinterpret_cast<const float4*>(lutT + x1o);
        const float4 B1 = *reinterpret_cast<const float4*>(lutT + 8192 + x2o);
        const float4 B2 = *reinterpret_cast<const float4*>(lutT + 16384 + x3o);

        const float4 cv = max4(add4(add4(A0, A1), A2),
                               add4(add4(B0, B1), B2));
        const float cur2[4] = {cv.x, cv.y, cv.z, cv.w};

        float pacc0 = 0.f, pacc1 = 0.f;
        #pragma unroll
        for (int j = 0; j < 4; j++) {
            float mm = fmaf(BETA, m2[j], cur2[j]);
            if (sp2[j]) mm -= th2;            // reset = previous spike
            m2[j] = mm;
            sp2[j] = mm > th2;
            if (sp2[j]) { pacc0 += fw0[j]; pacc1 += fw1[j]; }
        }
        // compress {l, l^8, l^16, l^24} -> lanes 0..7 store one STS.64
        pacc0 += __shfl_xor_sync(0xffffffffu, pacc0, 16);
        pacc1 += __shfl_xor_sync(0xffffffffu, pacc1, 16);
        pacc0 += __shfl_xor_sync(0xffffffffu, pacc0, 8);
        pacc1 += __shfl_xor_sync(0xffffffffu, pacc1, 8);
        if (lane < 8)
            raw[((t >> 3) & 1) * (T8 * 128) + (t & 7) * 128 + wrp * 8 + lane] =
                make_float2(pacc0, pacc1);

        if ((t & 7) == 7) {
            __syncthreads();
            // reduce this chunk (warps 0..15) writing g_partial directly;
            // other warps proceed to the next chunk's other raw buffer.
            if (wrp < 2 * T8) {
                const int tt = wrp >> 1, o = wrp & 1;
                const float* rf = reinterpret_cast<const float*>(
                    raw + ((t >> 3) & 1) * (T8 * 128) + tt * 128) + o;
                float s = 0.f;
                #pragma unroll
                for (int k = 0; k < 4; k++)
                    s += rf[(lane + 32 * k) * 2];
                #pragma unroll
                for (int offx = 16; offx > 0; offx >>= 1)
                    s += __shfl_xor_sync(0xffffffffu, s, offx);
                if (lane == 0)
                    gpart[((t & ~7) + tt) * 2 + o] = s;
            }
        }
    }
}

__global__ __launch_bounds__(64) void snn_final(
    const float* __restrict__ fcb,
    const float* __restrict__ thop,
    float* __restrict__ out)
{
    __shared__ float sm[NT][2];
    const int b = blockIdx.x;
    const int tid = threadIdx.x;

    {
        const int t = tid >> 1, o = tid & 1;
        float s = 0.f;
        #pragma unroll
        for (int tile = 0; tile < NTILE; tile++)
            s += g_partial[((b * NTILE + tile) * NT + t) * 2 + o];
        sm[t][o] = s;
    }
    __syncthreads();

    if (tid < 2) {
        const int o = tid;
        const float tho = *thop;
        const float fb = fcb[o];
        float mo = 0.f;
        for (int t = 0; t < NT; t++) {
            const float c = sm[t][o] + fb;
            const bool r = mo > tho;
            mo = BETA * mo + c;
            if (r) mo -= tho;
            const int base = (t * 256 + b) * 2 + o;
            out[base] = (mo > tho) ? 1.f : 0.f;   // spk_rec
            out[16384 + base] = mo;               // mem_rec
        }
    }
}

extern "C" void kernel_launch(void* const* d_in, const int* in_sizes, int n_in,
                              void* d_out, int out_size)
{
    const float* x    = (const float*)d_in[0];
    const float* w1   = (const float*)d_in[1];
    const float* b1   = (const float*)d_in[2];
    const float* w2   = (const float*)d_in[3];
    const float* b2   = (const float*)d_in[4];
    const float* fcw  = (const float*)d_in[5];
    const float* fcb  = (const float*)d_in[6];
    const float* th1  = (const float*)d_in[7];
    const float* th2  = (const float*)d_in[8];
    const float* tho  = (const float*)d_in[9];
    float* out = (float*)d_out;

    cudaFuncSetAttribute(snn_main, cudaFuncAttributeMaxDynamicSharedMemorySize,
                         SMEM_TOTAL);

    snn_l1<<<256 * 4, 512>>>(x, w1, b1, th1);
    snn_main<<<256 * NTILE, NTHR, SMEM_TOTAL>>>(w2, b2, fcw, th2);
    snn_final<<<256, 64>>>(fcb, tho, out);
}